// round 2
// baseline (speedup 1.0000x reference)
#include <cuda_runtime.h>

#define Nn   100000
#define Ee   3200000
#define HID  64
#define INF  500
#define CLS  40
#define KK   10

typedef unsigned long long ull;

// ---------------- device scratch (static; zero-initialized at load) ----------------
__device__ float g_buf0[Nn*HID];
__device__ float g_buf1[Nn*HID];
__device__ float g_buf2[Nn*HID];
__device__ float g_rst [Nn*HID];
__device__ ull   g_edge[Ee];                // packed {src, w}
__device__ int   g_rank[Ee];
__device__ int   g_rowptr[Nn+1];
__device__ int   g_cnt[Nn];
__device__ int   g_bsum[128];
__device__ float g_dots[(KK+1)*192];        // per-iter: d1[64] | d2[64] | d12[64]
__device__ float g_ss  [(KK+1)*64];         // per-iter column sum-of-squares
__device__ float g_inv [(KK+2)*HID];        // slot(i) at (i+1)*64 ; slot(-1)=slot0 stays zero

__device__ __forceinline__ float* bufptr(int i){
    return (i==0)? g_buf0 : (i==1)? g_buf1 : g_buf2;
}

// ---------------- init ----------------
__global__ void k_zero(){
    int i = blockIdx.x*blockDim.x + threadIdx.x;
    if (i < Nn) g_cnt[i] = 0;
    if (i < (KK+1)*192) g_dots[i] = 0.f;
    if (i < (KK+1)*64)  g_ss[i]   = 0.f;
}

// ---------------- CSR build ----------------
__global__ void k_count(const int* __restrict__ dst){
    int e = blockIdx.x*blockDim.x + threadIdx.x;
    if (e < Ee) g_rank[e] = atomicAdd(&g_cnt[dst[e]], 1);
}

__global__ void k_scan1(){          // per-block inclusive scan of g_cnt chunks of 1024
    __shared__ int s[1024];
    int t = threadIdx.x;
    int base = blockIdx.x*1024;
    int v = (base + t < Nn) ? g_cnt[base + t] : 0;
    s[t] = v; __syncthreads();
    for (int d = 1; d < 1024; d <<= 1){
        int add = (t >= d) ? s[t-d] : 0;
        __syncthreads();
        s[t] += add;
        __syncthreads();
    }
    if (base + t < Nn) g_rowptr[base + t + 1] = s[t];
    if (t == 1023) g_bsum[blockIdx.x] = s[1023];
}

__global__ void k_scan2(int nb){    // exclusive scan of block sums (small)
    __shared__ int s[128];
    int t = threadIdx.x;
    if (t < nb) s[t] = g_bsum[t];
    __syncthreads();
    if (t == 0){
        int acc = 0;
        for (int b = 0; b < nb; b++){ int v = s[b]; s[b] = acc; acc += v; }
    }
    __syncthreads();
    if (t < nb) g_bsum[t] = s[t];
}

__global__ void k_scan3(){
    int i = blockIdx.x*blockDim.x + threadIdx.x;
    if (i == 0) g_rowptr[0] = 0;
    if (i < Nn) g_rowptr[i+1] += g_bsum[i >> 10];
}

__global__ void k_scatter(const int* __restrict__ src, const int* __restrict__ dst,
                          const float* __restrict__ w){
    int e = blockIdx.x*blockDim.x + threadIdx.x;
    if (e >= Ee) return;
    int d   = dst[e];
    int pos = g_rowptr[d] + g_rank[e];
    ull pk = (unsigned int)src[e] | ((ull)__float_as_uint(w[e]) << 32);
    g_edge[pos] = pk;
}

// ---------------- fc1: U0 = relu(feat@W1 + b1) + 1e-5*noise ; col sumsq -> g_ss[0] ----------------
#define BM 128
#define BK 20
__global__ void k_fc1(const float* __restrict__ A, const float* __restrict__ W,
                      const float* __restrict__ b1, const float* __restrict__ noise){
    __shared__ float As[BK][132];
    __shared__ float Bs[BK][HID];
    __shared__ float scol[HID];
    int tid = threadIdx.x;
    int rowbase = blockIdx.x * BM;
    int tx = tid & 15;   // col group: cols tx*4..tx*4+3
    int ty = tid >> 4;   // row group: rows ty*8..ty*8+7
    float acc[8][4];
    #pragma unroll
    for (int i = 0; i < 8; i++)
        #pragma unroll
        for (int j = 0; j < 4; j++) acc[i][j] = 0.f;
    if (tid < HID) scol[tid] = 0.f;

    for (int k0 = 0; k0 < INF; k0 += BK){
        for (int f = tid; f < BM*BK; f += 256){
            int r = f / BK, k = f - r*BK;
            int grow = rowbase + r;
            As[k][r] = (grow < Nn) ? A[grow*INF + k0 + k] : 0.f;
        }
        for (int f = tid; f < BK*HID; f += 256){
            int k = f >> 6, c = f & 63;
            Bs[k][c] = W[(k0 + k)*HID + c];
        }
        __syncthreads();
        #pragma unroll
        for (int k = 0; k < BK; k++){
            float4 a0 = *(const float4*)&As[k][ty*8];
            float4 a1 = *(const float4*)&As[k][ty*8 + 4];
            float4 bq = *(const float4*)&Bs[k][tx*4];
            float av[8] = {a0.x,a0.y,a0.z,a0.w,a1.x,a1.y,a1.z,a1.w};
            float bv[4] = {bq.x,bq.y,bq.z,bq.w};
            #pragma unroll
            for (int i = 0; i < 8; i++)
                #pragma unroll
                for (int j = 0; j < 4; j++)
                    acc[i][j] = fmaf(av[i], bv[j], acc[i][j]);
        }
        __syncthreads();
    }

    float css[4] = {0.f,0.f,0.f,0.f};
    #pragma unroll
    for (int j = 0; j < 4; j++){
        int col = tx*4 + j;
        float bj = b1[col];
        #pragma unroll
        for (int i = 0; i < 8; i++){
            int grow = rowbase + ty*8 + i;
            if (grow < Nn){
                float v = fmaxf(acc[i][j] + bj, 0.f);
                v = fmaf(1e-5f, noise[grow*HID + col], v);
                g_buf0[grow*HID + col] = v;
                css[j] = fmaf(v, v, css[j]);
            }
        }
    }
    #pragma unroll
    for (int j = 0; j < 4; j++) atomicAdd(&scol[tx*4 + j], css[j]);
    __syncthreads();
    if (tid < HID) atomicAdd(&g_ss[tid], scol[tid]);
}

// ---------------- fused SpMM + dots ----------------
// R = inv_{i-1} .* (A @ U1)  (so R == A @ h_{i-1}),
// d1 = <R,U1>, d2 = <R,U2>, d12 = <U1,U2> per column -> g_dots[iter].
// Each block recomputes inv_{i-1} from g_ss[iter-1]; block 0 persists it to g_inv[iter].
__global__ void __launch_bounds__(256) k_spmm(int uIdx, int rIdx, int u2Idx, int iter, int hasU2){
    const float* __restrict__ U  = bufptr(uIdx);
    float* __restrict__ R        = bufptr(rIdx);
    const float* __restrict__ U2 = bufptr(u2Idx);
    __shared__ float inv_s[64];
    __shared__ float dots_s[192];
    __shared__ ull   est[8][32];
    int t = threadIdx.x;
    if (t < 64){
        float ss = g_ss[(iter-1)*64 + t];
        float iv = 1.f / fmaxf(sqrtf(ss), 1e-8f);
        inv_s[t] = iv;
        if (blockIdx.x == 0) g_inv[iter*64 + t] = iv;
    }
    if (t < 192) dots_s[t] = 0.f;
    __syncthreads();
    int wid  = t >> 5;
    int lane = t & 31;
    int gw = blockIdx.x*8 + wid;
    int nw = gridDim.x*8;
    float ivx = inv_s[2*lane], ivy = inv_s[2*lane+1];
    float d1x=0.f,d1y=0.f,d2x=0.f,d2y=0.f,d3x=0.f,d3y=0.f;

    for (int r = gw; r < Nn; r += nw){
        int e0 = g_rowptr[r], e1 = g_rowptr[r+1];
        float a0 = 0.f, a1 = 0.f;
        for (int base = e0; base < e1; base += 32){
            int m = e1 - base; if (m > 32) m = 32;
            if (lane < m) est[wid][lane] = g_edge[base + lane];
            __syncwarp();
            int j = 0;
            for (; j + 1 < m; j += 2){
                ull p0 = est[wid][j];
                ull p1 = est[wid][j+1];
                int   s0 = (int)(p0 & 0xffffffffu);
                float w0 = __uint_as_float((unsigned int)(p0 >> 32));
                int   s1 = (int)(p1 & 0xffffffffu);
                float w1 = __uint_as_float((unsigned int)(p1 >> 32));
                float2 v0 = *(const float2*)(U + (s0 << 6) + (lane << 1));
                float2 v1 = *(const float2*)(U + (s1 << 6) + (lane << 1));
                a0 = fmaf(w0, v0.x, a0); a1 = fmaf(w0, v0.y, a1);
                a0 = fmaf(w1, v1.x, a0); a1 = fmaf(w1, v1.y, a1);
            }
            if (j < m){
                ull p0 = est[wid][j];
                int   s0 = (int)(p0 & 0xffffffffu);
                float w0 = __uint_as_float((unsigned int)(p0 >> 32));
                float2 v0 = *(const float2*)(U + (s0 << 6) + (lane << 1));
                a0 = fmaf(w0, v0.x, a0); a1 = fmaf(w0, v0.y, a1);
            }
            __syncwarp();
        }
        float ox = a0 * ivx, oy = a1 * ivy;
        float2 o; o.x = ox; o.y = oy;
        *(float2*)(R + (r << 6) + (lane << 1)) = o;
        float2 u1 = *(const float2*)(U + (r << 6) + (lane << 1));
        d1x = fmaf(ox, u1.x, d1x); d1y = fmaf(oy, u1.y, d1y);
        if (hasU2){
            float2 u2 = *(const float2*)(U2 + (r << 6) + (lane << 1));
            d2x = fmaf(ox,   u2.x, d2x); d2y = fmaf(oy,   u2.y, d2y);
            d3x = fmaf(u1.x, u2.x, d3x); d3y = fmaf(u1.y, u2.y, d3y);
        }
    }
    atomicAdd(&dots_s[      2*lane], d1x); atomicAdd(&dots_s[      2*lane+1], d1y);
    if (hasU2){
        atomicAdd(&dots_s[ 64 + 2*lane], d2x); atomicAdd(&dots_s[ 64 + 2*lane+1], d2y);
        atomicAdd(&dots_s[128 + 2*lane], d3x); atomicAdd(&dots_s[128 + 2*lane+1], d3y);
    }
    __syncthreads();
    if (t < 192){
        float v = dots_s[t];
        if (v != 0.f || t < 64) atomicAdd(&g_dots[iter*192 + t], v);
    }
}

// ---------------- pass2: per-block coefficient recompute, subtract projections,
// sumsq -> g_ss[iter], deferred rst accumulation of alpha_{i-1} h_{i-1} ----------------
__global__ void __launch_bounds__(256) k_pass2(int rIdx, int u1Idx, int u2Idx, int iter,
                                               const float* __restrict__ alpha){
    float2* __restrict__ R        = (float2*)bufptr(rIdx);
    const float2* __restrict__ U1 = (const float2*)bufptr(u1Idx);
    const float2* __restrict__ U2 = (const float2*)bufptr(u2Idx);
    float2* __restrict__ RS = (float2*)g_rst;
    __shared__ float c1s[64], c2s[64], ras[64], sss[64];
    int t = threadIdx.x;
    if (t < 64){
        double inv1 = (double)g_inv[iter*64 + t];       // inv_{i-1}
        double inv2 = (double)g_inv[(iter-1)*64 + t];   // inv_{i-2} (slot0 zeros for i==1)
        double d1  = (double)g_dots[iter*192 + t];
        double d2  = (double)g_dots[iter*192 + 64 + t];
        double d12 = (double)g_dots[iter*192 + 128 + t];
        double c1  = d1*inv1*inv1;
        c1s[t] = (float)c1;                              // coeff on U1
        c2s[t] = (float)(inv2*inv2*(d2 - c1*d12));       // coeff on U2 (MGS-exact)
        ras[t] = alpha[t*(KK+1) + (iter-1)] * (float)inv1;
        sss[t] = 0.f;
    }
    __syncthreads();
    int c = t & 31;
    float c1x=c1s[2*c], c1y=c1s[2*c+1];
    float c2x=c2s[2*c], c2y=c2s[2*c+1];
    float rax=ras[2*c], ray=ras[2*c+1];
    float ssx=0.f, ssy=0.f;
    int tid = blockIdx.x*blockDim.x + t;
    int stride = gridDim.x*blockDim.x;
    if (iter == 1){
        for (int i = tid; i < Nn*32; i += stride){
            float2 r = R[i], u1 = U1[i];
            float wx = r.x - c1x*u1.x;
            float wy = r.y - c1y*u1.y;
            ssx = fmaf(wx, wx, ssx); ssy = fmaf(wy, wy, ssy);
            float2 o; o.x = wx; o.y = wy;
            R[i] = o;
            float2 rv; rv.x = rax*u1.x; rv.y = ray*u1.y;
            RS[i] = rv;
        }
    } else {
        for (int i = tid; i < Nn*32; i += stride){
            float2 r = R[i], u1 = U1[i], u2 = U2[i];
            float wx = r.x - c1x*u1.x - c2x*u2.x;
            float wy = r.y - c1y*u1.y - c2y*u2.y;
            ssx = fmaf(wx, wx, ssx); ssy = fmaf(wy, wy, ssy);
            float2 o; o.x = wx; o.y = wy;
            R[i] = o;
            float2 rv = RS[i];
            rv.x = fmaf(rax, u1.x, rv.x); rv.y = fmaf(ray, u1.y, rv.y);
            RS[i] = rv;
        }
    }
    atomicAdd(&sss[2*c], ssx); atomicAdd(&sss[2*c+1], ssy);
    __syncthreads();
    if (t < 64) atomicAdd(&g_ss[iter*64 + t], sss[t]);
}

// ---------------- final: out = (rst + a_K*inv_K .* U_K) @ W2 + b2 ----------------
__global__ void k_out(const float* __restrict__ W2, const float* __restrict__ b2,
                      const float* __restrict__ alpha, float* __restrict__ out, int ukIdx){
    const float* __restrict__ UK = bufptr(ukIdx);
    __shared__ float Ts[128][65];
    __shared__ float Bs[HID][CLS + 1];
    __shared__ float ck[64];
    int tid = threadIdx.x;
    int rowbase = blockIdx.x * 128;
    if (tid < 64){
        float ss  = g_ss[KK*64 + tid];
        float inv = 1.f / fmaxf(sqrtf(ss), 1e-8f);
        ck[tid] = alpha[tid*(KK+1) + KK] * inv;
    }
    for (int f = tid; f < HID*CLS; f += 256) Bs[f / CLS][f % CLS] = W2[f];
    __syncthreads();
    for (int f = tid; f < 128*64; f += 256){
        int r = f >> 6, col = f & 63;
        int grow = rowbase + r;
        float v = 0.f;
        if (grow < Nn){
            int idx = grow*64 + col;
            v = g_rst[idx] + ck[col]*UK[idx];
        }
        Ts[r][col] = v;
    }
    __syncthreads();
    int tr = tid & 31;   // rows tr*4..tr*4+3
    int tc = tid >> 5;   // cols tc*5..tc*5+4
    float acc[4][5];
    #pragma unroll
    for (int i = 0; i < 4; i++)
        #pragma unroll
        for (int j = 0; j < 5; j++) acc[i][j] = 0.f;
    for (int k = 0; k < 64; k++){
        float a[4], bb[5];
        #pragma unroll
        for (int i = 0; i < 4; i++) a[i] = Ts[tr*4 + i][k];
        #pragma unroll
        for (int j = 0; j < 5; j++) bb[j] = Bs[k][tc*5 + j];
        #pragma unroll
        for (int i = 0; i < 4; i++)
            #pragma unroll
            for (int j = 0; j < 5; j++)
                acc[i][j] = fmaf(a[i], bb[j], acc[i][j]);
    }
    #pragma unroll
    for (int i = 0; i < 4; i++){
        int row = rowbase + tr*4 + i;
        if (row < Nn){
            #pragma unroll
            for (int j = 0; j < 5; j++){
                int col = tc*5 + j;
                out[row*CLS + col] = acc[i][j] + b2[col];
            }
        }
    }
}

// ---------------- launch ----------------
extern "C" void kernel_launch(void* const* d_in, const int* in_sizes, int n_in,
                              void* d_out, int out_size){
    (void)in_sizes; (void)n_in; (void)out_size;
    const float* feat  = (const float*)d_in[0];
    const float* noise = (const float*)d_in[1];
    const float* normA = (const float*)d_in[2];
    const float* W1    = (const float*)d_in[3];
    const float* b1    = (const float*)d_in[4];
    const float* W2    = (const float*)d_in[5];
    const float* b2    = (const float*)d_in[6];
    const float* alpha = (const float*)d_in[7];
    const int*   ei    = (const int*)  d_in[8];
    const int* src = ei;
    const int* dst = ei + Ee;
    float* out = (float*)d_out;

    const int TB = 256;
    // CSR build (per call; deterministic work)
    k_zero   <<<(Nn + TB - 1)/TB, TB>>>();
    k_count  <<<(Ee + TB - 1)/TB, TB>>>(dst);
    k_scan1  <<<(Nn + 1023)/1024, 1024>>>();
    k_scan2  <<<1, 128>>>((Nn + 1023)/1024);
    k_scan3  <<<(Nn + TB - 1)/TB, TB>>>();
    k_scatter<<<(Ee + TB - 1)/TB, TB>>>(src, dst, normA);

    // fc1 -> U0 (unnormalized) + column sumsq -> g_ss[0]
    k_fc1<<<(Nn + 127)/128, 256>>>(feat, W1, b1, noise);

    for (int i = 1; i <= KK; i++){
        int rIdx = i % 3;
        int u1   = (i + 2) % 3;                 // U_{i-1}
        int u2   = (i == 1) ? 0 : (i + 1) % 3;  // U_{i-2} (unused for i==1)
        int hasU2 = (i == 1) ? 0 : 1;
        k_spmm <<<1024, TB>>>(u1, rIdx, u2, i, hasU2);
        k_pass2<<<1024, TB>>>(rIdx, u1, u2, i, alpha);
    }

    k_out<<<(Nn + 127)/128, 256>>>(W2, b2, alpha, out, KK % 3);
}

// round 3
// speedup vs baseline: 1.2822x; 1.2822x over previous
#include <cuda_runtime.h>

#define Nn   100000
#define Ee   3200000
#define HID  64
#define INF  500
#define CLS  40
#define KK   10

typedef unsigned long long ull;

// ---------------- device scratch (static; zero-initialized at load) ----------------
__device__ float g_buf0[Nn*HID];
__device__ float g_buf1[Nn*HID];
__device__ float g_buf2[Nn*HID];
__device__ float g_zbuf[Nn*HID];            // never written -> stays zero
__device__ float g_rst [Nn*HID];
__device__ ull   g_edge[Ee];                // packed {src, w}
__device__ int   g_rank[Ee];
__device__ int   g_rowptr[Nn+1];
__device__ int   g_cnt[Nn];
__device__ int   g_bsum[128];
__device__ float g_dots[(KK+1)*192];        // per-iter: d1[64] | d2[64] | d12[64]
__device__ float g_ss  [(KK+1)*64];         // per-iter column sum-of-squares
__device__ float g_inv [(KK+2)*HID];        // slot(i) at (i+1)*64 ; slot 0 (= inv_{-1}) stays zero

__device__ __forceinline__ float* bufptr(int i){
    return (i==0)? g_buf0 : (i==1)? g_buf1 : (i==2)? g_buf2 : g_zbuf;
}

// ---------------- init ----------------
__global__ void k_zero(){
    int i = blockIdx.x*blockDim.x + threadIdx.x;
    if (i < Nn) g_cnt[i] = 0;
    if (i < (KK+1)*192) g_dots[i] = 0.f;
    if (i < (KK+1)*64)  g_ss[i]   = 0.f;
}

// ---------------- CSR build ----------------
__global__ void k_count(const int* __restrict__ dst){
    int e = blockIdx.x*blockDim.x + threadIdx.x;
    if (e < Ee) g_rank[e] = atomicAdd(&g_cnt[dst[e]], 1);
}

__global__ void k_scan1(){          // per-block inclusive scan of g_cnt chunks of 1024
    __shared__ int s[1024];
    int t = threadIdx.x;
    int base = blockIdx.x*1024;
    int v = (base + t < Nn) ? g_cnt[base + t] : 0;
    s[t] = v; __syncthreads();
    for (int d = 1; d < 1024; d <<= 1){
        int add = (t >= d) ? s[t-d] : 0;
        __syncthreads();
        s[t] += add;
        __syncthreads();
    }
    if (base + t < Nn) g_rowptr[base + t + 1] = s[t];
    if (t == 1023) g_bsum[blockIdx.x] = s[1023];
}

__global__ void k_scan2(int nb){    // exclusive scan of block sums (small)
    __shared__ int s[128];
    int t = threadIdx.x;
    if (t < nb) s[t] = g_bsum[t];
    __syncthreads();
    if (t == 0){
        int acc = 0;
        for (int b = 0; b < nb; b++){ int v = s[b]; s[b] = acc; acc += v; }
    }
    __syncthreads();
    if (t < nb) g_bsum[t] = s[t];
}

__global__ void k_scan3(){
    int i = blockIdx.x*blockDim.x + threadIdx.x;
    if (i == 0) g_rowptr[0] = 0;
    if (i < Nn) g_rowptr[i+1] += g_bsum[i >> 10];
}

__global__ void k_scatter(const int* __restrict__ src, const int* __restrict__ dst,
                          const float* __restrict__ w){
    int e = blockIdx.x*blockDim.x + threadIdx.x;
    if (e >= Ee) return;
    int d   = dst[e];
    int pos = g_rowptr[d] + g_rank[e];
    ull pk = (unsigned int)src[e] | ((ull)__float_as_uint(w[e]) << 32);
    g_edge[pos] = pk;
}

// ---------------- fc1: U0 = relu(feat@W1 + b1) + 1e-5*noise ; col sumsq -> g_ss[0] ----------------
#define BM 128
#define BK 20
__global__ void k_fc1(const float* __restrict__ A, const float* __restrict__ W,
                      const float* __restrict__ b1, const float* __restrict__ noise){
    __shared__ float As[BK][132];
    __shared__ float Bs[BK][HID];
    __shared__ float scol[HID];
    int tid = threadIdx.x;
    int rowbase = blockIdx.x * BM;
    int tx = tid & 15;   // col group: cols tx*4..tx*4+3
    int ty = tid >> 4;   // row group: rows ty*8..ty*8+7
    float acc[8][4];
    #pragma unroll
    for (int i = 0; i < 8; i++)
        #pragma unroll
        for (int j = 0; j < 4; j++) acc[i][j] = 0.f;
    if (tid < HID) scol[tid] = 0.f;

    for (int k0 = 0; k0 < INF; k0 += BK){
        for (int f = tid; f < BM*BK; f += 256){
            int r = f / BK, k = f - r*BK;
            int grow = rowbase + r;
            As[k][r] = (grow < Nn) ? A[grow*INF + k0 + k] : 0.f;
        }
        for (int f = tid; f < BK*HID; f += 256){
            int k = f >> 6, c = f & 63;
            Bs[k][c] = W[(k0 + k)*HID + c];
        }
        __syncthreads();
        #pragma unroll
        for (int k = 0; k < BK; k++){
            float4 a0 = *(const float4*)&As[k][ty*8];
            float4 a1 = *(const float4*)&As[k][ty*8 + 4];
            float4 bq = *(const float4*)&Bs[k][tx*4];
            float av[8] = {a0.x,a0.y,a0.z,a0.w,a1.x,a1.y,a1.z,a1.w};
            float bv[4] = {bq.x,bq.y,bq.z,bq.w};
            #pragma unroll
            for (int i = 0; i < 8; i++)
                #pragma unroll
                for (int j = 0; j < 4; j++)
                    acc[i][j] = fmaf(av[i], bv[j], acc[i][j]);
        }
        __syncthreads();
    }

    float css[4] = {0.f,0.f,0.f,0.f};
    #pragma unroll
    for (int j = 0; j < 4; j++){
        int col = tx*4 + j;
        float bj = b1[col];
        #pragma unroll
        for (int i = 0; i < 8; i++){
            int grow = rowbase + ty*8 + i;
            if (grow < Nn){
                float v = fmaxf(acc[i][j] + bj, 0.f);
                v = fmaf(1e-5f, noise[grow*HID + col], v);
                g_buf0[grow*HID + col] = v;
                css[j] = fmaf(v, v, css[j]);
            }
        }
    }
    #pragma unroll
    for (int j = 0; j < 4; j++) atomicAdd(&scol[tx*4 + j], css[j]);
    __syncthreads();
    if (tid < HID) atomicAdd(&g_ss[tid], scol[tid]);
}

// ---------------- SpMM: R = inv_{i-1} .* (A @ U1), one warp per dst row (R1-proven structure) ----------------
__global__ void k_spmm(int uIdx, int rIdx, int iter){
    const float* __restrict__ U = bufptr(uIdx);
    float* __restrict__ R = bufptr(rIdx);
    __shared__ float inv_s[64];
    int t = threadIdx.x;
    if (t < 64){
        float ss = g_ss[(iter-1)*64 + t];
        float iv = 1.f / fmaxf(sqrtf(ss), 1e-8f);
        inv_s[t] = iv;
        if (blockIdx.x == 0) g_inv[iter*64 + t] = iv;
    }
    __syncthreads();
    int w    = (blockIdx.x*blockDim.x + t) >> 5;
    int lane = t & 31;
    if (w >= Nn) return;
    int e   = g_rowptr[w];
    int end = g_rowptr[w+1];
    float a0 = 0.f, a1 = 0.f;
    // unroll-4: 8 independent gathers in flight per lane
    for (; e + 3 < end; e += 4){
        ull p0 = g_edge[e];
        ull p1 = g_edge[e+1];
        ull p2 = g_edge[e+2];
        ull p3 = g_edge[e+3];
        int   s0 = (int)(p0 & 0xffffffffu); float w0 = __uint_as_float((unsigned int)(p0 >> 32));
        int   s1 = (int)(p1 & 0xffffffffu); float w1 = __uint_as_float((unsigned int)(p1 >> 32));
        int   s2 = (int)(p2 & 0xffffffffu); float w2 = __uint_as_float((unsigned int)(p2 >> 32));
        int   s3 = (int)(p3 & 0xffffffffu); float w3 = __uint_as_float((unsigned int)(p3 >> 32));
        float2 v0 = *(const float2*)(U + (s0 << 6) + (lane << 1));
        float2 v1 = *(const float2*)(U + (s1 << 6) + (lane << 1));
        float2 v2 = *(const float2*)(U + (s2 << 6) + (lane << 1));
        float2 v3 = *(const float2*)(U + (s3 << 6) + (lane << 1));
        a0 = fmaf(w0, v0.x, a0); a1 = fmaf(w0, v0.y, a1);
        a0 = fmaf(w1, v1.x, a0); a1 = fmaf(w1, v1.y, a1);
        a0 = fmaf(w2, v2.x, a0); a1 = fmaf(w2, v2.y, a1);
        a0 = fmaf(w3, v3.x, a0); a1 = fmaf(w3, v3.y, a1);
    }
    for (; e < end; e++){
        ull p0 = g_edge[e];
        int   s0 = (int)(p0 & 0xffffffffu);
        float w0 = __uint_as_float((unsigned int)(p0 >> 32));
        float2 v0 = *(const float2*)(U + (s0 << 6) + (lane << 1));
        a0 = fmaf(w0, v0.x, a0); a1 = fmaf(w0, v0.y, a1);
    }
    float2 o;
    o.x = a0 * inv_s[lane*2];
    o.y = a1 * inv_s[lane*2 + 1];
    *(float2*)(R + (w << 6) + (lane << 1)) = o;
}

// ---------------- dots: d1 = <R,U1>, d2 = <R,U2>, d12 = <U1,U2> per column -> g_dots[iter] ----------------
__global__ void k_dots(int rIdx, int u1Idx, int u2Idx, int iter){
    const float2* __restrict__ R  = (const float2*)bufptr(rIdx);
    const float2* __restrict__ U1 = (const float2*)bufptr(u1Idx);
    const float2* __restrict__ U2 = (const float2*)bufptr(u2Idx);
    int tid = blockIdx.x*blockDim.x + threadIdx.x;
    int stride = gridDim.x*blockDim.x;
    int c = threadIdx.x & 31;
    float d1x=0.f,d1y=0.f,d2x=0.f,d2y=0.f,d3x=0.f,d3y=0.f;
    for (int i = tid; i < Nn*32; i += stride){
        float2 r = R[i], u1 = U1[i], u2 = U2[i];
        d1x = fmaf(r.x,  u1.x, d1x); d1y = fmaf(r.y,  u1.y, d1y);
        d2x = fmaf(r.x,  u2.x, d2x); d2y = fmaf(r.y,  u2.y, d2y);
        d3x = fmaf(u1.x, u2.x, d3x); d3y = fmaf(u1.y, u2.y, d3y);
    }
    __shared__ float s[192];
    if (threadIdx.x < 192) s[threadIdx.x] = 0.f;
    __syncthreads();
    atomicAdd(&s[      c*2], d1x); atomicAdd(&s[      c*2+1], d1y);
    atomicAdd(&s[ 64 + c*2], d2x); atomicAdd(&s[ 64 + c*2+1], d2y);
    atomicAdd(&s[128 + c*2], d3x); atomicAdd(&s[128 + c*2+1], d3y);
    __syncthreads();
    if (threadIdx.x < 192) atomicAdd(&g_dots[iter*192 + threadIdx.x], s[threadIdx.x]);
}

// ---------------- pass2: in-block coefficient recompute (MGS-exact), subtract projections,
// sumsq -> g_ss[iter], deferred rst accumulation of alpha_{i-1} h_{i-1} ----------------
__global__ void k_pass2(int rIdx, int u1Idx, int u2Idx, int iter, int first,
                        const float* __restrict__ alpha){
    float2* __restrict__ R  = (float2*)bufptr(rIdx);
    const float2* __restrict__ U1 = (const float2*)bufptr(u1Idx);
    const float2* __restrict__ U2 = (const float2*)bufptr(u2Idx);
    float2* __restrict__ RS = (float2*)g_rst;
    __shared__ float c1s[64], c2s[64], ras[64], sss[64];
    int t = threadIdx.x;
    if (t < 64){
        double inv1 = (double)g_inv[iter*64 + t];       // inv_{i-1}
        double inv2 = (double)g_inv[(iter-1)*64 + t];   // inv_{i-2} (slot 0 zeros at i==1)
        double d1  = (double)g_dots[iter*192 + t];
        double d2  = (double)g_dots[iter*192 + 64 + t];
        double d12 = (double)g_dots[iter*192 + 128 + t];
        double c1  = d1*inv1*inv1;
        c1s[t] = (float)c1;                              // coeff on U1
        c2s[t] = (float)(inv2*inv2*(d2 - c1*d12));       // coeff on U2 (MGS-exact)
        ras[t] = alpha[t*(KK+1) + (iter-1)] * (float)inv1;
        sss[t] = 0.f;
    }
    __syncthreads();
    int c = t & 31;
    float c1x=c1s[2*c], c1y=c1s[2*c+1];
    float c2x=c2s[2*c], c2y=c2s[2*c+1];
    float rax=ras[2*c], ray=ras[2*c+1];
    float ssx=0.f, ssy=0.f;
    int tid = blockIdx.x*blockDim.x + t;
    int stride = gridDim.x*blockDim.x;
    for (int i = tid; i < Nn*32; i += stride){
        float2 r = R[i], u1 = U1[i], u2 = U2[i];
        float wx = r.x - c1x*u1.x - c2x*u2.x;
        float wy = r.y - c1y*u1.y - c2y*u2.y;
        ssx = fmaf(wx, wx, ssx); ssy = fmaf(wy, wy, ssy);
        float2 o; o.x = wx; o.y = wy;
        R[i] = o;
        float2 rv;
        if (first){ rv.x = rax*u1.x;            rv.y = ray*u1.y; }
        else      { rv = RS[i]; rv.x = fmaf(rax, u1.x, rv.x); rv.y = fmaf(ray, u1.y, rv.y); }
        RS[i] = rv;
    }
    atomicAdd(&sss[2*c], ssx); atomicAdd(&sss[2*c+1], ssy);
    __syncthreads();
    if (t < 64) atomicAdd(&g_ss[iter*64 + t], sss[t]);
}

// ---------------- final: out = (rst + a_K*inv_K .* U_K) @ W2 + b2 ----------------
__global__ void k_out(const float* __restrict__ W2, const float* __restrict__ b2,
                      const float* __restrict__ alpha, float* __restrict__ out, int ukIdx){
    const float* __restrict__ UK = bufptr(ukIdx);
    __shared__ float Ts[128][65];
    __shared__ float Bs[HID][CLS + 1];
    __shared__ float ck[64];
    int tid = threadIdx.x;
    int rowbase = blockIdx.x * 128;
    if (tid < 64){
        float ss  = g_ss[KK*64 + tid];
        float inv = 1.f / fmaxf(sqrtf(ss), 1e-8f);
        ck[tid] = alpha[tid*(KK+1) + KK] * inv;
    }
    for (int f = tid; f < HID*CLS; f += 256) Bs[f / CLS][f % CLS] = W2[f];
    __syncthreads();
    for (int f = tid; f < 128*64; f += 256){
        int r = f >> 6, col = f & 63;
        int grow = rowbase + r;
        float v = 0.f;
        if (grow < Nn){
            int idx = grow*64 + col;
            v = g_rst[idx] + ck[col]*UK[idx];
        }
        Ts[r][col] = v;
    }
    __syncthreads();
    int tr = tid & 31;   // rows tr*4..tr*4+3
    int tc = tid >> 5;   // cols tc*5..tc*5+4
    float acc[4][5];
    #pragma unroll
    for (int i = 0; i < 4; i++)
        #pragma unroll
        for (int j = 0; j < 5; j++) acc[i][j] = 0.f;
    for (int k = 0; k < 64; k++){
        float a[4], bb[5];
        #pragma unroll
        for (int i = 0; i < 4; i++) a[i] = Ts[tr*4 + i][k];
        #pragma unroll
        for (int j = 0; j < 5; j++) bb[j] = Bs[k][tc*5 + j];
        #pragma unroll
        for (int i = 0; i < 4; i++)
            #pragma unroll
            for (int j = 0; j < 5; j++)
                acc[i][j] = fmaf(a[i], bb[j], acc[i][j]);
    }
    #pragma unroll
    for (int i = 0; i < 4; i++){
        int row = rowbase + tr*4 + i;
        if (row < Nn){
            #pragma unroll
            for (int j = 0; j < 5; j++){
                int col = tc*5 + j;
                out[row*CLS + col] = acc[i][j] + b2[col];
            }
        }
    }
}

// ---------------- launch ----------------
extern "C" void kernel_launch(void* const* d_in, const int* in_sizes, int n_in,
                              void* d_out, int out_size){
    (void)in_sizes; (void)n_in; (void)out_size;
    const float* feat  = (const float*)d_in[0];
    const float* noise = (const float*)d_in[1];
    const float* normA = (const float*)d_in[2];
    const float* W1    = (const float*)d_in[3];
    const float* b1    = (const float*)d_in[4];
    const float* W2    = (const float*)d_in[5];
    const float* b2    = (const float*)d_in[6];
    const float* alpha = (const float*)d_in[7];
    const int*   ei    = (const int*)  d_in[8];
    const int* src = ei;
    const int* dst = ei + Ee;
    float* out = (float*)d_out;

    const int TB = 256;
    // CSR build (per call; deterministic work)
    k_zero   <<<(Nn + TB - 1)/TB, TB>>>();
    k_count  <<<(Ee + TB - 1)/TB, TB>>>(dst);
    k_scan1  <<<(Nn + 1023)/1024, 1024>>>();
    k_scan2  <<<1, 128>>>((Nn + 1023)/1024);
    k_scan3  <<<(Nn + TB - 1)/TB, TB>>>();
    k_scatter<<<(Ee + TB - 1)/TB, TB>>>(src, dst, normA);

    // fc1 -> U0 (unnormalized) + column sumsq -> g_ss[0]
    k_fc1<<<(Nn + 127)/128, 256>>>(feat, W1, b1, noise);

    for (int i = 1; i <= KK; i++){
        int rIdx = i % 3;
        int u1   = (i + 2) % 3;                 // U_{i-1}
        int u2   = (i == 1) ? 3 : (i + 1) % 3;  // U_{i-2} (zero buffer for i==1)
        k_spmm <<<(Nn*32 + TB - 1)/TB, TB>>>(u1, rIdx, i);
        k_dots <<<1520, TB>>>(rIdx, u1, u2, i);
        k_pass2<<<1520, TB>>>(rIdx, u1, u2, i, (i == 1) ? 1 : 0, alpha);
    }

    k_out<<<(Nn + 127)/128, 256>>>(W2, b2, alpha, out, KK % 3);
}

// round 4
// speedup vs baseline: 1.3870x; 1.0817x over previous
#include <cuda_runtime.h>

#define Nn   100000
#define Ee   3200000
#define HID  64
#define INF  500
#define CLS  40
#define KK   10

typedef unsigned long long ull;

#define FFMA2(acc, a, b) asm("fma.rn.f32x2 %0, %1, %2, %0;" : "+l"(acc) : "l"(a), "l"(b))
__device__ __forceinline__ ull dup2(float v){
    ull r; asm("mov.b64 %0, {%1, %1};" : "=l"(r) : "f"(v)); return r;
}
__device__ __forceinline__ void unpk2(ull p, float& lo, float& hi){
    asm("mov.b64 {%0, %1}, %2;" : "=f"(lo), "=f"(hi) : "l"(p));
}

// ---------------- device scratch (static; zero-initialized at load) ----------------
__device__ float g_buf0[Nn*HID];
__device__ float g_buf1[Nn*HID];
__device__ float g_buf2[Nn*HID];
__device__ float g_zbuf[Nn*HID];            // never written -> stays zero
__device__ float g_rst [Nn*HID];
__device__ ull   g_edge[Ee];                // packed {src, w}
__device__ int   g_rank[Ee];
__device__ int   g_rowptr[Nn+1];
__device__ int   g_cnt[Nn];
__device__ int   g_bsum[128];
__device__ float g_dots[(KK+1)*192];        // per-iter: d1[64] | d2[64] | d12[64]
__device__ float g_ss  [(KK+1)*64];         // per-iter column sum-of-squares
__device__ float g_inv [(KK+2)*HID];        // slot(i) at (i+1)*64 ; slot 0 (= inv_{-1}) stays zero

__device__ __forceinline__ float* bufptr(int i){
    return (i==0)? g_buf0 : (i==1)? g_buf1 : (i==2)? g_buf2 : g_zbuf;
}

// ---------------- init ----------------
__global__ void k_zero(){
    int i = blockIdx.x*blockDim.x + threadIdx.x;
    if (i < Nn) g_cnt[i] = 0;
    if (i < (KK+1)*192) g_dots[i] = 0.f;
    if (i < (KK+1)*64)  g_ss[i]   = 0.f;
}

// ---------------- CSR build ----------------
__global__ void k_count(const int* __restrict__ dst){
    int e = blockIdx.x*blockDim.x + threadIdx.x;
    if (e < Ee) g_rank[e] = atomicAdd(&g_cnt[dst[e]], 1);
}

__global__ void k_scan1(){          // per-block inclusive scan of g_cnt chunks of 1024
    __shared__ int s[1024];
    int t = threadIdx.x;
    int base = blockIdx.x*1024;
    int v = (base + t < Nn) ? g_cnt[base + t] : 0;
    s[t] = v; __syncthreads();
    for (int d = 1; d < 1024; d <<= 1){
        int add = (t >= d) ? s[t-d] : 0;
        __syncthreads();
        s[t] += add;
        __syncthreads();
    }
    if (base + t < Nn) g_rowptr[base + t + 1] = s[t];
    if (t == 1023) g_bsum[blockIdx.x] = s[1023];
}

__global__ void k_scan2(int nb){    // exclusive scan of block sums (small)
    __shared__ int s[128];
    int t = threadIdx.x;
    if (t < nb) s[t] = g_bsum[t];
    __syncthreads();
    if (t == 0){
        int acc = 0;
        for (int b = 0; b < nb; b++){ int v = s[b]; s[b] = acc; acc += v; }
    }
    __syncthreads();
    if (t < nb) g_bsum[t] = s[t];
}

__global__ void k_scan3(){
    int i = blockIdx.x*blockDim.x + threadIdx.x;
    if (i == 0) g_rowptr[0] = 0;
    if (i < Nn) g_rowptr[i+1] += g_bsum[i >> 10];
}

__global__ void k_scatter(const int* __restrict__ src, const int* __restrict__ dst,
                          const float* __restrict__ w){
    int e = blockIdx.x*blockDim.x + threadIdx.x;
    if (e >= Ee) return;
    int d   = dst[e];
    int pos = g_rowptr[d] + g_rank[e];
    ull pk = (unsigned int)src[e] | ((ull)__float_as_uint(w[e]) << 32);
    g_edge[pos] = pk;
}

// ---------------- fc1: U0 = relu(feat@W1 + b1) + 1e-5*noise ; col sumsq -> g_ss[0] ----------------
// 256-row x 64-col tile, 256 threads, each 8 rows x 8 cols, f32x2 packed accumulators (FFMA2).
#define FBM 256
#define FBK 20
__global__ void __launch_bounds__(256) k_fc1(const float* __restrict__ A, const float* __restrict__ W,
                      const float* __restrict__ b1, const float* __restrict__ noise){
    __shared__ float As[FBK][FBM + 8];      // row stride 264 floats (8B/16B aligned)
    __shared__ float Bs[FBK][HID + 4];
    __shared__ float scol[HID];
    int tid = threadIdx.x;
    int rowbase = blockIdx.x * FBM;
    int tx = tid & 7;    // cols tx*8 .. tx*8+7
    int ty = tid >> 3;   // rows ty*8 .. ty*8+7 (ty 0..31)

    ull acc[4][8];       // [row-pair p = rows 2p,2p+1][col j]
    #pragma unroll
    for (int p = 0; p < 4; p++)
        #pragma unroll
        for (int j = 0; j < 8; j++) acc[p][j] = 0ull;
    if (tid < HID) scol[tid] = 0.f;

    for (int k0 = 0; k0 < INF; k0 += FBK){
        // load A tile: 256 rows x 20 k, via float4 (4 k's per load), transposed store
        #pragma unroll
        for (int f = tid; f < FBM*5; f += 256){
            int r = f / 5, q = f - r*5;
            int grow = rowbase + r;
            float4 v = make_float4(0.f,0.f,0.f,0.f);
            if (grow < Nn) v = *(const float4*)(A + grow*INF + k0 + q*4);
            As[q*4+0][r] = v.x; As[q*4+1][r] = v.y;
            As[q*4+2][r] = v.z; As[q*4+3][r] = v.w;
        }
        // load B tile: 20 x 64
        #pragma unroll
        for (int f = tid; f < FBK*16; f += 256){
            int k = f >> 4, c = f & 15;
            *(float4*)&Bs[k][c*4] = *(const float4*)(W + (k0 + k)*HID + c*4);
        }
        __syncthreads();
        #pragma unroll
        for (int k = 0; k < FBK; k++){
            const ull* Ap = (const ull*)&As[k][ty*8];   // 4 row-pairs, LDS.64 each
            ull ap0 = Ap[0], ap1 = Ap[1], ap2 = Ap[2], ap3 = Ap[3];
            float4 bq0 = *(const float4*)&Bs[k][tx*8];
            float4 bq1 = *(const float4*)&Bs[k][tx*8 + 4];
            ull bd[8];
            bd[0]=dup2(bq0.x); bd[1]=dup2(bq0.y); bd[2]=dup2(bq0.z); bd[3]=dup2(bq0.w);
            bd[4]=dup2(bq1.x); bd[5]=dup2(bq1.y); bd[6]=dup2(bq1.z); bd[7]=dup2(bq1.w);
            #pragma unroll
            for (int j = 0; j < 8; j++){
                FFMA2(acc[0][j], ap0, bd[j]);
                FFMA2(acc[1][j], ap1, bd[j]);
                FFMA2(acc[2][j], ap2, bd[j]);
                FFMA2(acc[3][j], ap3, bd[j]);
            }
        }
        __syncthreads();
    }

    float bj[8];
    *(float4*)&bj[0] = *(const float4*)(b1 + tx*8);
    *(float4*)&bj[4] = *(const float4*)(b1 + tx*8 + 4);
    float css[8] = {0.f,0.f,0.f,0.f,0.f,0.f,0.f,0.f};

    #pragma unroll
    for (int p = 0; p < 4; p++){
        float o0[8], o1[8];
        #pragma unroll
        for (int j = 0; j < 8; j++) unpk2(acc[p][j], o0[j], o1[j]);
        #pragma unroll
        for (int half = 0; half < 2; half++){
            float* o = half ? o1 : o0;
            int grow = rowbase + ty*8 + 2*p + half;
            if (grow < Nn){
                const float* nz = noise + grow*HID + tx*8;
                float4 n0 = *(const float4*)nz;
                float4 n1 = *(const float4*)(nz + 4);
                float nv[8] = {n0.x,n0.y,n0.z,n0.w,n1.x,n1.y,n1.z,n1.w};
                float v[8];
                #pragma unroll
                for (int j = 0; j < 8; j++){
                    float x = fmaxf(o[j] + bj[j], 0.f);
                    x = fmaf(1e-5f, nv[j], x);
                    v[j] = x;
                    css[j] = fmaf(x, x, css[j]);
                }
                float* dstp = g_buf0 + grow*HID + tx*8;
                *(float4*)dstp       = make_float4(v[0],v[1],v[2],v[3]);
                *(float4*)(dstp + 4) = make_float4(v[4],v[5],v[6],v[7]);
            }
        }
    }
    __syncthreads();   // scol zeroed by threads < 64 above
    #pragma unroll
    for (int j = 0; j < 8; j++) atomicAdd(&scol[tx*8 + j], css[j]);
    __syncthreads();
    if (tid < HID) atomicAdd(&g_ss[tid], scol[tid]);
}

// ---------------- SpMM: R = inv_{i-1} .* (A @ U1), one warp per dst row (R1-proven structure) ----------------
__global__ void k_spmm(int uIdx, int rIdx, int iter){
    const float* __restrict__ U = bufptr(uIdx);
    float* __restrict__ R = bufptr(rIdx);
    __shared__ float inv_s[64];
    int t = threadIdx.x;
    if (t < 64){
        float ss = g_ss[(iter-1)*64 + t];
        float iv = 1.f / fmaxf(sqrtf(ss), 1e-8f);
        inv_s[t] = iv;
        if (blockIdx.x == 0) g_inv[iter*64 + t] = iv;
    }
    __syncthreads();
    int w    = (blockIdx.x*blockDim.x + t) >> 5;
    int lane = t & 31;
    if (w >= Nn) return;
    int e   = g_rowptr[w];
    int end = g_rowptr[w+1];
    float a0 = 0.f, a1 = 0.f;
    for (; e + 3 < end; e += 4){
        ull p0 = g_edge[e];
        ull p1 = g_edge[e+1];
        ull p2 = g_edge[e+2];
        ull p3 = g_edge[e+3];
        int   s0 = (int)(p0 & 0xffffffffu); float w0 = __uint_as_float((unsigned int)(p0 >> 32));
        int   s1 = (int)(p1 & 0xffffffffu); float w1 = __uint_as_float((unsigned int)(p1 >> 32));
        int   s2 = (int)(p2 & 0xffffffffu); float w2 = __uint_as_float((unsigned int)(p2 >> 32));
        int   s3 = (int)(p3 & 0xffffffffu); float w3 = __uint_as_float((unsigned int)(p3 >> 32));
        float2 v0 = *(const float2*)(U + (s0 << 6) + (lane << 1));
        float2 v1 = *(const float2*)(U + (s1 << 6) + (lane << 1));
        float2 v2 = *(const float2*)(U + (s2 << 6) + (lane << 1));
        float2 v3 = *(const float2*)(U + (s3 << 6) + (lane << 1));
        a0 = fmaf(w0, v0.x, a0); a1 = fmaf(w0, v0.y, a1);
        a0 = fmaf(w1, v1.x, a0); a1 = fmaf(w1, v1.y, a1);
        a0 = fmaf(w2, v2.x, a0); a1 = fmaf(w2, v2.y, a1);
        a0 = fmaf(w3, v3.x, a0); a1 = fmaf(w3, v3.y, a1);
    }
    for (; e < end; e++){
        ull p0 = g_edge[e];
        int   s0 = (int)(p0 & 0xffffffffu);
        float w0 = __uint_as_float((unsigned int)(p0 >> 32));
        float2 v0 = *(const float2*)(U + (s0 << 6) + (lane << 1));
        a0 = fmaf(w0, v0.x, a0); a1 = fmaf(w0, v0.y, a1);
    }
    float2 o;
    o.x = a0 * inv_s[lane*2];
    o.y = a1 * inv_s[lane*2 + 1];
    *(float2*)(R + (w << 6) + (lane << 1)) = o;
}

// ---------------- dots: d1 = <R,U1>, d2 = <R,U2>, d12 = <U1,U2> per column -> g_dots[iter] ----------------
__global__ void k_dots(int rIdx, int u1Idx, int u2Idx, int iter){
    const float4* __restrict__ R  = (const float4*)bufptr(rIdx);
    const float4* __restrict__ U1 = (const float4*)bufptr(u1Idx);
    const float4* __restrict__ U2 = (const float4*)bufptr(u2Idx);
    int tid = blockIdx.x*blockDim.x + threadIdx.x;
    int stride = gridDim.x*blockDim.x;           // multiple of 16
    int c4 = (threadIdx.x & 15) * 4;             // this thread's 4 columns
    float4 d1 = make_float4(0,0,0,0), d2 = d1, d3 = d1;
    for (int i = tid; i < Nn*16; i += stride){
        float4 r = R[i], u1 = U1[i], u2 = U2[i];
        d1.x = fmaf(r.x,  u1.x, d1.x); d1.y = fmaf(r.y,  u1.y, d1.y);
        d1.z = fmaf(r.z,  u1.z, d1.z); d1.w = fmaf(r.w,  u1.w, d1.w);
        d2.x = fmaf(r.x,  u2.x, d2.x); d2.y = fmaf(r.y,  u2.y, d2.y);
        d2.z = fmaf(r.z,  u2.z, d2.z); d2.w = fmaf(r.w,  u2.w, d2.w);
        d3.x = fmaf(u1.x, u2.x, d3.x); d3.y = fmaf(u1.y, u2.y, d3.y);
        d3.z = fmaf(u1.z, u2.z, d3.z); d3.w = fmaf(u1.w, u2.w, d3.w);
    }
    __shared__ float s[192];
    if (threadIdx.x < 192) s[threadIdx.x] = 0.f;
    __syncthreads();
    atomicAdd(&s[      c4  ], d1.x); atomicAdd(&s[      c4+1], d1.y);
    atomicAdd(&s[      c4+2], d1.z); atomicAdd(&s[      c4+3], d1.w);
    atomicAdd(&s[ 64 + c4  ], d2.x); atomicAdd(&s[ 64 + c4+1], d2.y);
    atomicAdd(&s[ 64 + c4+2], d2.z); atomicAdd(&s[ 64 + c4+3], d2.w);
    atomicAdd(&s[128 + c4  ], d3.x); atomicAdd(&s[128 + c4+1], d3.y);
    atomicAdd(&s[128 + c4+2], d3.z); atomicAdd(&s[128 + c4+3], d3.w);
    __syncthreads();
    if (threadIdx.x < 192) atomicAdd(&g_dots[iter*192 + threadIdx.x], s[threadIdx.x]);
}

// ---------------- pass2: in-block coefficient recompute (MGS-exact), subtract projections,
// sumsq -> g_ss[iter], deferred rst accumulation of alpha_{i-1} h_{i-1} ----------------
__global__ void k_pass2(int rIdx, int u1Idx, int u2Idx, int iter, int first,
                        const float* __restrict__ alpha){
    float4* __restrict__ R  = (float4*)bufptr(rIdx);
    const float4* __restrict__ U1 = (const float4*)bufptr(u1Idx);
    const float4* __restrict__ U2 = (const float4*)bufptr(u2Idx);
    float4* __restrict__ RS = (float4*)g_rst;
    __shared__ float c1s[64], c2s[64], ras[64], sss[64];
    int t = threadIdx.x;
    if (t < 64){
        double inv1 = (double)g_inv[iter*64 + t];       // inv_{i-1}
        double inv2 = (double)g_inv[(iter-1)*64 + t];   // inv_{i-2} (slot 0 zeros at i==1)
        double d1  = (double)g_dots[iter*192 + t];
        double d2  = (double)g_dots[iter*192 + 64 + t];
        double d12 = (double)g_dots[iter*192 + 128 + t];
        double c1  = d1*inv1*inv1;
        c1s[t] = (float)c1;                              // coeff on U1
        c2s[t] = (float)(inv2*inv2*(d2 - c1*d12));       // coeff on U2 (MGS-exact)
        ras[t] = alpha[t*(KK+1) + (iter-1)] * (float)inv1;
        sss[t] = 0.f;
    }
    __syncthreads();
    int c4 = (t & 15) * 4;
    float4 c1v = *(const float4*)&c1s[c4];
    float4 c2v = *(const float4*)&c2s[c4];
    float4 rav = *(const float4*)&ras[c4];
    float4 ss  = make_float4(0,0,0,0);
    int tid = blockIdx.x*blockDim.x + t;
    int stride = gridDim.x*blockDim.x;
    for (int i = tid; i < Nn*16; i += stride){
        float4 r = R[i], u1 = U1[i], u2 = U2[i];
        float4 w;
        w.x = r.x - c1v.x*u1.x - c2v.x*u2.x;
        w.y = r.y - c1v.y*u1.y - c2v.y*u2.y;
        w.z = r.z - c1v.z*u1.z - c2v.z*u2.z;
        w.w = r.w - c1v.w*u1.w - c2v.w*u2.w;
        ss.x = fmaf(w.x, w.x, ss.x); ss.y = fmaf(w.y, w.y, ss.y);
        ss.z = fmaf(w.z, w.z, ss.z); ss.w = fmaf(w.w, w.w, ss.w);
        R[i] = w;
        float4 rv;
        if (first){
            rv.x = rav.x*u1.x; rv.y = rav.y*u1.y;
            rv.z = rav.z*u1.z; rv.w = rav.w*u1.w;
        } else {
            rv = RS[i];
            rv.x = fmaf(rav.x, u1.x, rv.x); rv.y = fmaf(rav.y, u1.y, rv.y);
            rv.z = fmaf(rav.z, u1.z, rv.z); rv.w = fmaf(rav.w, u1.w, rv.w);
        }
        RS[i] = rv;
    }
    atomicAdd(&sss[c4  ], ss.x); atomicAdd(&sss[c4+1], ss.y);
    atomicAdd(&sss[c4+2], ss.z); atomicAdd(&sss[c4+3], ss.w);
    __syncthreads();
    if (t < 64) atomicAdd(&g_ss[iter*64 + t], sss[t]);
}

// ---------------- final: out = (rst + a_K*inv_K .* U_K) @ W2 + b2 ----------------
__global__ void k_out(const float* __restrict__ W2, const float* __restrict__ b2,
                      const float* __restrict__ alpha, float* __restrict__ out, int ukIdx){
    const float* __restrict__ UK = bufptr(ukIdx);
    __shared__ float Ts[128][65];
    __shared__ float Bs[HID][CLS + 1];
    __shared__ float ck[64];
    int tid = threadIdx.x;
    int rowbase = blockIdx.x * 128;
    if (tid < 64){
        float ss  = g_ss[KK*64 + tid];
        float inv = 1.f / fmaxf(sqrtf(ss), 1e-8f);
        ck[tid] = alpha[tid*(KK+1) + KK] * inv;
    }
    for (int f = tid; f < HID*CLS; f += 256) Bs[f / CLS][f % CLS] = W2[f];
    __syncthreads();
    for (int f = tid; f < 128*64; f += 256){
        int r = f >> 6, col = f & 63;
        int grow = rowbase + r;
        float v = 0.f;
        if (grow < Nn){
            int idx = grow*64 + col;
            v = g_rst[idx] + ck[col]*UK[idx];
        }
        Ts[r][col] = v;
    }
    __syncthreads();
    int tr = tid & 31;   // rows tr*4..tr*4+3
    int tc = tid >> 5;   // cols tc*5..tc*5+4
    float acc[4][5];
    #pragma unroll
    for (int i = 0; i < 4; i++)
        #pragma unroll
        for (int j = 0; j < 5; j++) acc[i][j] = 0.f;
    for (int k = 0; k < 64; k++){
        float a[4], bb[5];
        #pragma unroll
        for (int i = 0; i < 4; i++) a[i] = Ts[tr*4 + i][k];
        #pragma unroll
        for (int j = 0; j < 5; j++) bb[j] = Bs[k][tc*5 + j];
        #pragma unroll
        for (int i = 0; i < 4; i++)
            #pragma unroll
            for (int j = 0; j < 5; j++)
                acc[i][j] = fmaf(a[i], bb[j], acc[i][j]);
    }
    #pragma unroll
    for (int i = 0; i < 4; i++){
        int row = rowbase + tr*4 + i;
        if (row < Nn){
            #pragma unroll
            for (int j = 0; j < 5; j++){
                int col = tc*5 + j;
                out[row*CLS + col] = acc[i][j] + b2[col];
            }
        }
    }
}

// ---------------- launch ----------------
extern "C" void kernel_launch(void* const* d_in, const int* in_sizes, int n_in,
                              void* d_out, int out_size){
    (void)in_sizes; (void)n_in; (void)out_size;
    const float* feat  = (const float*)d_in[0];
    const float* noise = (const float*)d_in[1];
    const float* normA = (const float*)d_in[2];
    const float* W1    = (const float*)d_in[3];
    const float* b1    = (const float*)d_in[4];
    const float* W2    = (const float*)d_in[5];
    const float* b2    = (const float*)d_in[6];
    const float* alpha = (const float*)d_in[7];
    const int*   ei    = (const int*)  d_in[8];
    const int* src = ei;
    const int* dst = ei + Ee;
    float* out = (float*)d_out;

    const int TB = 256;
    // CSR build (per call; deterministic work)
    k_zero   <<<(Nn + TB - 1)/TB, TB>>>();
    k_count  <<<(Ee + TB - 1)/TB, TB>>>(dst);
    k_scan1  <<<(Nn + 1023)/1024, 1024>>>();
    k_scan2  <<<1, 128>>>((Nn + 1023)/1024);
    k_scan3  <<<(Nn + TB - 1)/TB, TB>>>();
    k_scatter<<<(Ee + TB - 1)/TB, TB>>>(src, dst, normA);

    // fc1 -> U0 (unnormalized) + column sumsq -> g_ss[0]
    k_fc1<<<(Nn + FBM - 1)/FBM, 256>>>(feat, W1, b1, noise);

    for (int i = 1; i <= KK; i++){
        int rIdx = i % 3;
        int u1   = (i + 2) % 3;                 // U_{i-1}
        int u2   = (i == 1) ? 3 : (i + 1) % 3;  // U_{i-2} (zero buffer for i==1)
        k_spmm <<<(Nn*32 + TB - 1)/TB, TB>>>(u1, rIdx, i);
        k_dots <<<1520, TB>>>(rIdx, u1, u2, i);
        k_pass2<<<1520, TB>>>(rIdx, u1, u2, i, (i == 1) ? 1 : 0, alpha);
    }

    k_out<<<(Nn + 127)/128, 256>>>(W2, b2, alpha, out, KK % 3);
}